// round 6
// baseline (speedup 1.0000x reference)
#include <cuda_runtime.h>
#include <math.h>
#include <stdint.h>

#define NN 4096
#define DD 128
#define EPSF 1e-12f
#define SPLITK 4
#define KCHUNK (NN / SPLITK)   // 1024
#define BM 64
#define BK 32
#define NIT (KCHUNK / BK)      // 32
#define SA 68                  // A smem m-stride (64 + pad)
#define SB 136                 // B smem n-stride (128 + pad)

// ---------------- device scratch (no allocations allowed) ----------------
__device__ float g_att[(size_t)NN * NN];        // dense attention input, 64 MB
__device__ float g_feat[NN * DD];               // W @ activities
__device__ float g_norm[NN];                    // row sums of att
__device__ float g_part[SPLITK][NN * DD];       // split-K partials, 8 MB
__device__ int   g_cnt[NN];                     // edges per target
__device__ int   g_off[NN];                     // exclusive prefix
__device__ int   g_cur[NN];                     // scatter cursors
__device__ int   g_eid[1 << 20];                // permuted edge ids
__device__ int   g_ec[1 << 20];                 // permuted current ids
__device__ int   g_idx64;                       // 1 if indices are int64

// ---------------- helpers ----------------
__device__ __forceinline__ uint32_t cvt_tf32(float f) {
    uint32_t o;
    asm("cvt.rna.tf32.f32 %0, %1;" : "=r"(o) : "f"(f));
    return o;
}

__device__ __forceinline__ void mma_tf32(float* c, const uint32_t* a, const uint32_t* b) {
    asm volatile(
        "mma.sync.aligned.m16n8k8.row.col.f32.tf32.tf32.f32 "
        "{%0,%1,%2,%3},{%4,%5,%6,%7},{%8,%9},{%0,%1,%2,%3};"
        : "+f"(c[0]), "+f"(c[1]), "+f"(c[2]), "+f"(c[3])
        : "r"(a[0]), "r"(a[1]), "r"(a[2]), "r"(a[3]), "r"(b[0]), "r"(b[1]));
}

__device__ __forceinline__ int load_idx(const void* raw, int e) {
    if (g_idx64) return (int)((const long long*)raw)[e];
    return ((const int*)raw)[e];
}

// ---------------- detect int32 vs int64 index dtype ----------------
__global__ void detect_kernel(const int* __restrict__ cur) {
    if (threadIdx.x == 0 && blockIdx.x == 0) {
        bool is64 = true;
        #pragma unroll
        for (int i = 0; i < 8; i++) {
            int lo = cur[2 * i];
            int hi = cur[2 * i + 1];
            if (lo < 0 || lo >= NN) is64 = false;
            if (hi != 0) is64 = false;
        }
        g_idx64 = is64 ? 1 : 0;
    }
}

// ---------------- zero bin counters ----------------
__global__ void zero_cnt_kernel() {
    int i = blockIdx.x * blockDim.x + threadIdx.x;
    if (i < NN) g_cnt[i] = 0;
}

// ---------------- histogram over targets ----------------
__global__ __launch_bounds__(256) void hist_kernel(const void* __restrict__ tgt, int E) {
    int e = blockIdx.x * blockDim.x + threadIdx.x;
    if (e < E) atomicAdd(&g_cnt[load_idx(tgt, e)], 1);
}

// ---------------- exclusive scan of 4096 counts (single block, shfl) -------
__global__ __launch_bounds__(256) void scan_kernel() {
    __shared__ int wsum[8];
    int tid = threadIdx.x, lane = tid & 31, warp = tid >> 5;
    int base = tid * 16;
    // 4 independent int4 loads (MLP=4 overlaps DRAM/L2 latency)
    int4 v0 = reinterpret_cast<const int4*>(g_cnt)[tid * 4 + 0];
    int4 v1 = reinterpret_cast<const int4*>(g_cnt)[tid * 4 + 1];
    int4 v2 = reinterpret_cast<const int4*>(g_cnt)[tid * 4 + 2];
    int4 v3 = reinterpret_cast<const int4*>(g_cnt)[tid * 4 + 3];
    int c[16] = {v0.x, v0.y, v0.z, v0.w, v1.x, v1.y, v1.z, v1.w,
                 v2.x, v2.y, v2.z, v2.w, v3.x, v3.y, v3.z, v3.w};
    int local[16];
    int s = 0;
    #pragma unroll
    for (int j = 0; j < 16; j++) { local[j] = s; s += c[j]; }
    int v = s;
    #pragma unroll
    for (int o = 1; o < 32; o <<= 1) {
        int u = __shfl_up_sync(0xffffffffu, v, o);
        if (lane >= o) v += u;
    }
    if (lane == 31) wsum[warp] = v;
    __syncthreads();
    if (warp == 0) {
        int w = (lane < 8) ? wsum[lane] : 0;
        #pragma unroll
        for (int o = 1; o < 8; o <<= 1) {
            int u = __shfl_up_sync(0xffffffffu, w, o);
            if (lane >= o) w += u;
        }
        if (lane < 8) wsum[lane] = w;
    }
    __syncthreads();
    int excl = v - s + (warp ? wsum[warp - 1] : 0);
    #pragma unroll
    for (int j = 0; j < 16; j++) {
        int o = excl + local[j];
        g_off[base + j] = o;
        g_cur[base + j] = o;
    }
}

// ---------------- scatter edge ids into bins ----------------
__global__ __launch_bounds__(256) void scatter_kernel(
    const void* __restrict__ cur, const void* __restrict__ tgt, int E) {
    int e = blockIdx.x * blockDim.x + threadIdx.x;
    if (e < E) {
        int t = load_idx(tgt, e);
        int c = load_idx(cur, e);
        int pos = atomicAdd(&g_cur[t], 1);
        g_eid[pos] = e;
        g_ec[pos] = c;
    }
}

// ---------------- binned edge pass: one block per target row ----------------
__global__ __launch_bounds__(256) void binned_edge_kernel(
    const float* __restrict__ act, const float* __restrict__ cases) {
    __shared__ __align__(16) float s_att[NN];
    __shared__ float s_red[8];
    int t = blockIdx.x;
    int tid = threadIdx.x, lane = tid & 31, warp = tid >> 5;

    for (int j = tid; j < NN / 4; j += 256)
        reinterpret_cast<float4*>(s_att)[j] = make_float4(0.f, 0.f, 0.f, 0.f);

    float4 t4 = reinterpret_cast<const float4*>(act + (size_t)t * DD)[lane];
    __syncthreads();

    int beg = g_off[t], cnt = g_cnt[t];
    for (int i = warp; i < cnt; i += 8) {
        int e = g_eid[beg + i];
        int c = g_ec[beg + i];
        float4 c4 = reinterpret_cast<const float4*>(cases + (size_t)e * DD)[lane];
        float4 h4 = reinterpret_cast<const float4*>(act + (size_t)c * DD)[lane];
        float dx = h4.x + c4.x - t4.x;
        float dy = h4.y + c4.y - t4.y;
        float dz = h4.z + c4.z - t4.z;
        float dw = h4.w + c4.w - t4.w;
        float s = dx * dx + dy * dy + dz * dz + dw * dw;
        #pragma unroll
        for (int o = 16; o; o >>= 1) s += __shfl_xor_sync(0xffffffffu, s, o);
        if (lane == 0) atomicAdd(&s_att[c], __expf(-sqrtf(s)));
    }
    __syncthreads();

    float sum = 0.f;
    for (int j = tid; j < NN / 4; j += 256) {
        float4 v = reinterpret_cast<float4*>(s_att)[j];
        sum += v.x + v.y + v.z + v.w;
        reinterpret_cast<float4*>(g_att + (size_t)t * NN)[j] = v;
    }
    #pragma unroll
    for (int o = 16; o; o >>= 1) sum += __shfl_xor_sync(0xffffffffu, sum, o);
    if (lane == 0) s_red[warp] = sum;
    __syncthreads();
    if (warp == 0) {
        float x = (lane < 8) ? s_red[lane] : 0.f;
        #pragma unroll
        for (int o = 4; o; o >>= 1) x += __shfl_xor_sync(0xffffffffu, x, o);
        if (lane == 0) g_norm[t] = x;
    }
}

// ---------------- tf32 tensor-core GEMM, split-K (BM=64, 2 CTAs/SM) --------
// mode 0: A = W (arg),  B = act (arg)
// mode 1: A = g_att,    B = g_feat
__global__ __launch_bounds__(256, 2) void mma_gemm_kernel(
    const float* __restrict__ A_arg, const float* __restrict__ B_arg, int mode) {
    __shared__ uint32_t As[BK * SA];   // [k][m], padded stride 68
    __shared__ uint32_t Bs[BK * SB];   // [k][n], padded stride 136

    const float* A = (mode == 0) ? A_arg : g_att;
    const float* B = (mode == 0) ? B_arg : g_feat;

    int tid = threadIdx.x;
    int m0 = blockIdx.x * BM;
    int kb0 = blockIdx.y * KCHUNK;

    int lane = tid & 31, warp = tid >> 5;
    int wm = warp >> 2, wn = warp & 3;       // 2 x 4 warp grid, warp tile 32x32
    int g = lane >> 2, tc = lane & 3;
    int mbase = wm * 32, nbase = wn * 32;

    float acc[2][4][4];
    #pragma unroll
    for (int mi = 0; mi < 2; mi++)
        #pragma unroll
        for (int ni = 0; ni < 4; ni++)
            #pragma unroll
            for (int q = 0; q < 4; q++) acc[mi][ni][q] = 0.f;

    float4 ar[2], br[4];
    // prefetch tile 0: A 64x32 = 512 float4 (2/thr), B 32x128 = 1024 float4 (4/thr)
    #pragma unroll
    for (int j = 0; j < 2; j++) {
        int id = tid + j * 256;
        ar[j] = *reinterpret_cast<const float4*>(
            A + (size_t)(m0 + (id >> 3)) * NN + kb0 + (id & 7) * 4);
    }
    #pragma unroll
    for (int j = 0; j < 4; j++) {
        int id = tid + j * 256;
        br[j] = *reinterpret_cast<const float4*>(
            B + (size_t)(kb0 + (id >> 5)) * DD + (id & 31) * 4);
    }

    for (int it = 0; it < NIT; it++) {
        // stage registers -> smem (with tf32 rounding)
        #pragma unroll
        for (int j = 0; j < 2; j++) {
            int id = tid + j * 256;
            int r = id >> 3, c4 = id & 7;
            As[(c4 * 4 + 0) * SA + r] = cvt_tf32(ar[j].x);
            As[(c4 * 4 + 1) * SA + r] = cvt_tf32(ar[j].y);
            As[(c4 * 4 + 2) * SA + r] = cvt_tf32(ar[j].z);
            As[(c4 * 4 + 3) * SA + r] = cvt_tf32(ar[j].w);
        }
        #pragma unroll
        for (int j = 0; j < 4; j++) {
            int id = tid + j * 256;
            int rb = id >> 5, bc4 = id & 31;
            uint32_t* bp = &Bs[rb * SB + bc4 * 4];
            bp[0] = cvt_tf32(br[j].x);
            bp[1] = cvt_tf32(br[j].y);
            bp[2] = cvt_tf32(br[j].z);
            bp[3] = cvt_tf32(br[j].w);
        }
        __syncthreads();

        // prefetch next tile (overlaps with compute below)
        if (it + 1 < NIT) {
            int kb = kb0 + (it + 1) * BK;
            #pragma unroll
            for (int j = 0; j < 2; j++) {
                int id = tid + j * 256;
                ar[j] = *reinterpret_cast<const float4*>(
                    A + (size_t)(m0 + (id >> 3)) * NN + kb + (id & 7) * 4);
            }
            #pragma unroll
            for (int j = 0; j < 4; j++) {
                int id = tid + j * 256;
                br[j] = *reinterpret_cast<const float4*>(
                    B + (size_t)(kb + (id >> 5)) * DD + (id & 31) * 4);
            }
        }

        // compute on current tile
        #pragma unroll
        for (int ks = 0; ks < 4; ks++) {
            int k0 = ks * 8;
            uint32_t a[2][4], b[4][2];
            const uint32_t* Ar0 = &As[(k0 + tc) * SA];
            const uint32_t* Ar1 = &As[(k0 + tc + 4) * SA];
            #pragma unroll
            for (int mi = 0; mi < 2; mi++) {
                int m = mbase + mi * 16 + g;
                a[mi][0] = Ar0[m];
                a[mi][1] = Ar0[m + 8];
                a[mi][2] = Ar1[m];
                a[mi][3] = Ar1[m + 8];
            }
            const uint32_t* Br0 = &Bs[(k0 + tc) * SB];
            const uint32_t* Br1 = &Bs[(k0 + tc + 4) * SB];
            #pragma unroll
            for (int ni = 0; ni < 4; ni++) {
                int n = nbase + ni * 8 + g;
                b[ni][0] = Br0[n];
                b[ni][1] = Br1[n];
            }
            #pragma unroll
            for (int mi = 0; mi < 2; mi++)
                #pragma unroll
                for (int ni = 0; ni < 4; ni++)
                    mma_tf32(acc[mi][ni], a[mi], b[ni]);
        }
        __syncthreads();
    }

    float* P = g_part[blockIdx.y];
    #pragma unroll
    for (int mi = 0; mi < 2; mi++) {
        #pragma unroll
        for (int ni = 0; ni < 4; ni++) {
            int r = m0 + mbase + mi * 16 + g;
            int cc = nbase + ni * 8 + tc * 2;
            *reinterpret_cast<float2*>(&P[(size_t)r * DD + cc]) =
                make_float2(acc[mi][ni][0], acc[mi][ni][1]);
            *reinterpret_cast<float2*>(&P[(size_t)(r + 8) * DD + cc]) =
                make_float2(acc[mi][ni][2], acc[mi][ni][3]);
        }
    }
}

// ---------------- split-K reduce (+ epilogue for mode 1) ----------------
__global__ __launch_bounds__(256) void reduce_kernel(float* __restrict__ out, int mode) {
    int i = blockIdx.x * blockDim.x + threadIdx.x;   // float4 index
    float4 s = reinterpret_cast<const float4*>(g_part[0])[i];
    #pragma unroll
    for (int p = 1; p < SPLITK; p++) {
        float4 v = reinterpret_cast<const float4*>(g_part[p])[i];
        s.x += v.x; s.y += v.y; s.z += v.z; s.w += v.w;
    }
    if (mode == 1) {
        int row = i >> 5;                       // 32 float4 per row (DD=128)
        float inv = 1.0f / (g_norm[row] + EPSF);
        float4 f = reinterpret_cast<const float4*>(g_feat)[i];
        s.x = s.x * inv + f.x;
        s.y = s.y * inv + f.y;
        s.z = s.z * inv + f.z;
        s.w = s.w * inv + f.w;
        reinterpret_cast<float4*>(out)[i] = s;
    } else {
        reinterpret_cast<float4*>(g_feat)[i] = s;
    }
}

// ---------------- launch ----------------
extern "C" void kernel_launch(void* const* d_in, const int* in_sizes, int n_in,
                              void* d_out, int out_size) {
    const void* cur = d_in[0];
    const void* tgt = d_in[1];
    const float* act = (const float*)d_in[2];
    const float* cases = (const float*)d_in[3];
    const float* W = (const float*)d_in[4];
    int E = in_sizes[0];
    float* out = (float*)d_out;

    detect_kernel<<<1, 32>>>((const int*)cur);
    zero_cnt_kernel<<<16, 256>>>();

    int eb = (E + 255) / 256;
    hist_kernel<<<eb, 256>>>(tgt, E);
    scan_kernel<<<1, 256>>>();
    scatter_kernel<<<eb, 256>>>(cur, tgt, E);
    binned_edge_kernel<<<NN, 256>>>(act, cases);

    dim3 ggrid(NN / BM, SPLITK);
    int rblocks = (NN * DD / 4) / 256;

    mma_gemm_kernel<<<ggrid, 256>>>(W, act, 0);            // parts = W @ act
    reduce_kernel<<<rblocks, 256>>>(out, 0);               // g_feat = sum(parts)
    mma_gemm_kernel<<<ggrid, 256>>>(nullptr, nullptr, 1);  // parts = att @ feat
    reduce_kernel<<<rblocks, 256>>>(out, 1);               // out = norm(parts)+feat
}

// round 7
// speedup vs baseline: 1.1885x; 1.1885x over previous
#include <cuda_runtime.h>
#include <math.h>
#include <stdint.h>

#define NN 4096
#define DD 128
#define EPSF 1e-12f
#define SPLITK 8
#define KCHUNK (NN / SPLITK)   // 512
#define BM 128
#define BK 32
#define NIT (KCHUNK / BK)      // 16
#define SA 132
#define SB 132

// ---------------- device scratch (no allocations allowed) ----------------
__device__ float g_feat[NN * DD];               // W @ activities
__device__ float g_part[SPLITK][NN * DD];       // split-K partials, 16 MB
__device__ int   g_cnt[NN];                     // edges per target
__device__ int   g_off[NN];                     // exclusive prefix
__device__ int   g_cur[NN];                     // scatter cursors
__device__ int   g_eid[1 << 20];                // permuted edge ids
__device__ int   g_ec[1 << 20];                 // permuted current ids
__device__ int   g_idx64;                       // 1 if indices are int64

// ---------------- helpers ----------------
__device__ __forceinline__ uint32_t cvt_tf32(float f) {
    uint32_t o;
    asm("cvt.rna.tf32.f32 %0, %1;" : "=r"(o) : "f"(f));
    return o;
}

__device__ __forceinline__ void mma_tf32(float* c, const uint32_t* a, const uint32_t* b) {
    asm volatile(
        "mma.sync.aligned.m16n8k8.row.col.f32.tf32.tf32.f32 "
        "{%0,%1,%2,%3},{%4,%5,%6,%7},{%8,%9},{%0,%1,%2,%3};"
        : "+f"(c[0]), "+f"(c[1]), "+f"(c[2]), "+f"(c[3])
        : "r"(a[0]), "r"(a[1]), "r"(a[2]), "r"(a[3]), "r"(b[0]), "r"(b[1]));
}

__device__ __forceinline__ int load_idx(const void* raw, int e) {
    if (g_idx64) return (int)((const long long*)raw)[e];
    return ((const int*)raw)[e];
}

// ---------------- detect int32 vs int64 index dtype ----------------
__global__ void detect_kernel(const int* __restrict__ cur) {
    if (threadIdx.x == 0 && blockIdx.x == 0) {
        bool is64 = true;
        #pragma unroll
        for (int i = 0; i < 8; i++) {
            int lo = cur[2 * i];
            int hi = cur[2 * i + 1];
            if (lo < 0 || lo >= NN) is64 = false;
            if (hi != 0) is64 = false;
        }
        g_idx64 = is64 ? 1 : 0;
    }
}

// ---------------- zero bin counters ----------------
__global__ void zero_cnt_kernel() {
    int i = blockIdx.x * blockDim.x + threadIdx.x;
    if (i < NN) g_cnt[i] = 0;
}

// ---------------- histogram over targets ----------------
__global__ __launch_bounds__(256) void hist_kernel(const void* __restrict__ tgt, int E) {
    int e = blockIdx.x * blockDim.x + threadIdx.x;
    if (e < E) atomicAdd(&g_cnt[load_idx(tgt, e)], 1);
}

// ---------------- exclusive scan of 4096 counts (single block, shfl) -------
__global__ __launch_bounds__(256) void scan_kernel() {
    __shared__ int wsum[8];
    int tid = threadIdx.x, lane = tid & 31, warp = tid >> 5;
    int base = tid * 16;
    int4 v0 = reinterpret_cast<const int4*>(g_cnt)[tid * 4 + 0];
    int4 v1 = reinterpret_cast<const int4*>(g_cnt)[tid * 4 + 1];
    int4 v2 = reinterpret_cast<const int4*>(g_cnt)[tid * 4 + 2];
    int4 v3 = reinterpret_cast<const int4*>(g_cnt)[tid * 4 + 3];
    int c[16] = {v0.x, v0.y, v0.z, v0.w, v1.x, v1.y, v1.z, v1.w,
                 v2.x, v2.y, v2.z, v2.w, v3.x, v3.y, v3.z, v3.w};
    int local[16];
    int s = 0;
    #pragma unroll
    for (int j = 0; j < 16; j++) { local[j] = s; s += c[j]; }
    int v = s;
    #pragma unroll
    for (int o = 1; o < 32; o <<= 1) {
        int u = __shfl_up_sync(0xffffffffu, v, o);
        if (lane >= o) v += u;
    }
    if (lane == 31) wsum[warp] = v;
    __syncthreads();
    if (warp == 0) {
        int w = (lane < 8) ? wsum[lane] : 0;
        #pragma unroll
        for (int o = 1; o < 8; o <<= 1) {
            int u = __shfl_up_sync(0xffffffffu, w, o);
            if (lane >= o) w += u;
        }
        if (lane < 8) wsum[lane] = w;
    }
    __syncthreads();
    int excl = v - s + (warp ? wsum[warp - 1] : 0);
    #pragma unroll
    for (int j = 0; j < 16; j++) {
        int o = excl + local[j];
        g_off[base + j] = o;
        g_cur[base + j] = o;
    }
}

// ---------------- scatter edge ids into bins ----------------
__global__ __launch_bounds__(256) void scatter_kernel(
    const void* __restrict__ cur, const void* __restrict__ tgt, int E) {
    int e = blockIdx.x * blockDim.x + threadIdx.x;
    if (e < E) {
        int t = load_idx(tgt, e);
        int c = load_idx(cur, e);
        int pos = atomicAdd(&g_cur[t], 1);
        g_eid[pos] = e;
        g_ec[pos] = c;
    }
}

// ---------------- fused edge + SpMM pass: one block per target row ---------
// out[t] = (sum_e val_e * feat[c_e]) / (norm_t + eps) + feat[t]
__global__ __launch_bounds__(256) void fused_edge_kernel(
    const float* __restrict__ act, const float* __restrict__ cases,
    float* __restrict__ out) {
    __shared__ __align__(16) float s_acc[8][DD];   // per-warp accumulators
    __shared__ float s_nrm[8];
    int t = blockIdx.x;
    int tid = threadIdx.x, lane = tid & 31, warp = tid >> 5;

    float4 t4 = reinterpret_cast<const float4*>(act + (size_t)t * DD)[lane];
    float4 acc = make_float4(0.f, 0.f, 0.f, 0.f);
    float nrm = 0.f;

    int beg = g_off[t], cnt = g_cnt[t];
    for (int i = warp; i < cnt; i += 8) {
        int e = g_eid[beg + i];
        int c = g_ec[beg + i];
        float4 c4 = reinterpret_cast<const float4*>(cases + (size_t)e * DD)[lane];
        float4 h4 = reinterpret_cast<const float4*>(act + (size_t)c * DD)[lane];
        float dx = h4.x + c4.x - t4.x;
        float dy = h4.y + c4.y - t4.y;
        float dz = h4.z + c4.z - t4.z;
        float dw = h4.w + c4.w - t4.w;
        float s = dx * dx + dy * dy + dz * dz + dw * dw;
        #pragma unroll
        for (int o = 16; o; o >>= 1) s += __shfl_xor_sync(0xffffffffu, s, o);
        float val = __expf(-sqrtf(s));    // same value in all lanes
        nrm += val;
        float4 f4 = reinterpret_cast<const float4*>(g_feat + (size_t)c * DD)[lane];
        acc.x += val * f4.x;
        acc.y += val * f4.y;
        acc.z += val * f4.z;
        acc.w += val * f4.w;
    }

    reinterpret_cast<float4*>(&s_acc[warp][0])[lane] = acc;
    if (lane == 0) s_nrm[warp] = nrm;
    __syncthreads();

    if (tid < DD) {
        float v = 0.f, nn = 0.f;
        #pragma unroll
        for (int w = 0; w < 8; w++) { v += s_acc[w][tid]; nn += s_nrm[w]; }
        float inv = 1.0f / (nn + EPSF);
        out[(size_t)t * DD + tid] = v * inv + g_feat[(size_t)t * DD + tid];
    }
}

// ---------------- tf32 tensor-core GEMM, split-K (round-4 config) ----------
// parts[split] = W[4096, KCHUNK] * act[KCHUNK, 128]
__global__ __launch_bounds__(256) void mma_gemm_kernel(
    const float* __restrict__ A, const float* __restrict__ B) {
    __shared__ uint32_t As[BK * SA];   // [k][m], padded stride 132
    __shared__ uint32_t Bs[BK * SB];   // [k][n], padded stride 132

    int tid = threadIdx.x;
    int m0 = blockIdx.x * BM;
    int kb0 = blockIdx.y * KCHUNK;

    int lane = tid & 31, warp = tid >> 5;
    int wr = warp >> 1, wc = warp & 1;       // 4 x 2 warp grid
    int g = lane >> 2, tc = lane & 3;
    int mbase = wr * 32, nbase = wc * 64;

    float acc[2][8][4];
    #pragma unroll
    for (int mi = 0; mi < 2; mi++)
        #pragma unroll
        for (int ni = 0; ni < 8; ni++)
            #pragma unroll
            for (int q = 0; q < 4; q++) acc[mi][ni][q] = 0.f;

    float4 ar[4], br[4];
    #pragma unroll
    for (int j = 0; j < 4; j++) {
        int id = tid + j * 256;
        ar[j] = *reinterpret_cast<const float4*>(
            A + (size_t)(m0 + (id >> 3)) * NN + kb0 + (id & 7) * 4);
        br[j] = *reinterpret_cast<const float4*>(
            B + (size_t)(kb0 + (id >> 5)) * DD + (id & 31) * 4);
    }

    for (int it = 0; it < NIT; it++) {
        #pragma unroll
        for (int j = 0; j < 4; j++) {
            int id = tid + j * 256;
            int r = id >> 3, c4 = id & 7;
            As[(c4 * 4 + 0) * SA + r] = cvt_tf32(ar[j].x);
            As[(c4 * 4 + 1) * SA + r] = cvt_tf32(ar[j].y);
            As[(c4 * 4 + 2) * SA + r] = cvt_tf32(ar[j].z);
            As[(c4 * 4 + 3) * SA + r] = cvt_tf32(ar[j].w);
            int rb = id >> 5, bc4 = id & 31;
            uint32_t* bp = &Bs[rb * SB + bc4 * 4];
            bp[0] = cvt_tf32(br[j].x);
            bp[1] = cvt_tf32(br[j].y);
            bp[2] = cvt_tf32(br[j].z);
            bp[3] = cvt_tf32(br[j].w);
        }
        __syncthreads();

        if (it + 1 < NIT) {
            int kb = kb0 + (it + 1) * BK;
            #pragma unroll
            for (int j = 0; j < 4; j++) {
                int id = tid + j * 256;
                ar[j] = *reinterpret_cast<const float4*>(
                    A + (size_t)(m0 + (id >> 3)) * NN + kb + (id & 7) * 4);
                br[j] = *reinterpret_cast<const float4*>(
                    B + (size_t)(kb + (id >> 5)) * DD + (id & 31) * 4);
            }
        }

        #pragma unroll
        for (int ks = 0; ks < 4; ks++) {
            int k0 = ks * 8;
            uint32_t a[2][4], b[8][2];
            const uint32_t* Ar0 = &As[(k0 + tc) * SA];
            const uint32_t* Ar1 = &As[(k0 + tc + 4) * SA];
            #pragma unroll
            for (int mi = 0; mi < 2; mi++) {
                int m = mbase + mi * 16 + g;
                a[mi][0] = Ar0[m];
                a[mi][1] = Ar0[m + 8];
                a[mi][2] = Ar1[m];
                a[mi][3] = Ar1[m + 8];
            }
            const uint32_t* Br0 = &Bs[(k0 + tc) * SB];
            const uint32_t* Br1 = &Bs[(k0 + tc + 4) * SB];
            #pragma unroll
            for (int ni = 0; ni < 8; ni++) {
                int n = nbase + ni * 8 + g;
                b[ni][0] = Br0[n];
                b[ni][1] = Br1[n];
            }
            #pragma unroll
            for (int mi = 0; mi < 2; mi++)
                #pragma unroll
                for (int ni = 0; ni < 8; ni++)
                    mma_tf32(acc[mi][ni], a[mi], b[ni]);
        }
        __syncthreads();
    }

    float* P = g_part[blockIdx.y];
    #pragma unroll
    for (int mi = 0; mi < 2; mi++) {
        #pragma unroll
        for (int ni = 0; ni < 8; ni++) {
            int r = m0 + mbase + mi * 16 + g;
            int cc = nbase + ni * 8 + tc * 2;
            *reinterpret_cast<float2*>(&P[(size_t)r * DD + cc]) =
                make_float2(acc[mi][ni][0], acc[mi][ni][1]);
            *reinterpret_cast<float2*>(&P[(size_t)(r + 8) * DD + cc]) =
                make_float2(acc[mi][ni][2], acc[mi][ni][3]);
        }
    }
}

// ---------------- split-K reduce: g_feat = sum(parts) ----------------
__global__ __launch_bounds__(256) void reduce_kernel() {
    int i = blockIdx.x * blockDim.x + threadIdx.x;   // float4 index
    float4 s = reinterpret_cast<const float4*>(g_part[0])[i];
    #pragma unroll
    for (int p = 1; p < SPLITK; p++) {
        float4 v = reinterpret_cast<const float4*>(g_part[p])[i];
        s.x += v.x; s.y += v.y; s.z += v.z; s.w += v.w;
    }
    reinterpret_cast<float4*>(g_feat)[i] = s;
}

// ---------------- launch ----------------
extern "C" void kernel_launch(void* const* d_in, const int* in_sizes, int n_in,
                              void* d_out, int out_size) {
    const void* cur = d_in[0];
    const void* tgt = d_in[1];
    const float* act = (const float*)d_in[2];
    const float* cases = (const float*)d_in[3];
    const float* W = (const float*)d_in[4];
    int E = in_sizes[0];
    float* out = (float*)d_out;

    detect_kernel<<<1, 32>>>((const int*)cur);
    zero_cnt_kernel<<<16, 256>>>();

    int eb = (E + 255) / 256;
    hist_kernel<<<eb, 256>>>(tgt, E);
    scan_kernel<<<1, 256>>>();
    scatter_kernel<<<eb, 256>>>(cur, tgt, E);

    dim3 ggrid(NN / BM, SPLITK);
    int rblocks = (NN * DD / 4) / 256;
    mma_gemm_kernel<<<ggrid, 256>>>(W, act);     // parts = W @ act
    reduce_kernel<<<rblocks, 256>>>();           // g_feat = sum(parts)

    fused_edge_kernel<<<NN, 256>>>(act, cases, out);
}